// round 1
// baseline (speedup 1.0000x reference)
#include <cuda_runtime.h>
#include <math.h>

#define NB 18
#define TC 128
#define NPAIR 1500          // pair = a*30 + p,  a in [0,50), p in [0,30)
#define ACC_PITCH 1536      // multiple of 32 -> bank(acc) = pair % 32 (conflict-free scatter)
#define AMPT_PITCH 53
#define NTHREADS 512
#define NBLOCKS 640         // (b*c) * s = 32 * 20

// smem layout (byte offsets)
#define OFF_ACC   0
#define OFF_CNT   110592                  // 18*1536*4
#define OFF_AMPT  112752                  // + 540*4
#define OFF_BINS  139888                  // + 128*53*4
#define OFF_CUT   143848                  // + 30*132
#define SMEM_BYTES 143936

__device__ float g_mi[(size_t)NBLOCKS * NPAIR];

__global__ void __launch_bounds__(NTHREADS, 1)
mi_kernel(const float* __restrict__ pha,
          const float* __restrict__ amp,
          const float* __restrict__ cut_g)
{
    extern __shared__ char sm[];
    float*         acc    = (float*)(sm + OFF_ACC);
    int*           counts = (int*)  (sm + OFF_CNT);
    float*         ampT   = (float*)(sm + OFF_AMPT);
    unsigned char* bins   = (unsigned char*)(sm + OFF_BINS);
    const unsigned* bins32 = (const unsigned*)(sm + OFF_BINS);
    float*         cut    = (float*)(sm + OFF_CUT);

    const int tid = threadIdx.x;
    const int bc  = blockIdx.x / 20;   // 0..31
    const int s   = blockIdx.x % 20;   // 0..19

    // zero accumulators & counts, stage cutoffs
    for (int i = tid; i < NB * ACC_PITCH; i += NTHREADS) acc[i] = 0.0f;
    for (int i = tid; i < 30 * NB; i += NTHREADS) counts[i] = 0;
    if (tid < 19) cut[tid] = cut_g[tid];
    __syncthreads();

    // keep cutoffs in registers for the bin computation
    float cutr[19];
    #pragma unroll
    for (int j = 0; j < 19; ++j) cutr[j] = cut[j];

    // base pointers for this (bc, s)
    const float* pha_base = pha + ((size_t)bc * 30 * 20 + s) * 1024;
    const float* amp_base = amp + ((size_t)bc * 50 * 20 + s) * 1024;

    // pair assignment: 3 independent chains per thread for ILP
    const int pair0 = tid;
    const int pair1 = tid + NTHREADS;
    const int pair2 = tid + 2 * NTHREADS;
    const bool has2 = (pair2 < NPAIR);
    const int p0 = pair0 % 30, a0 = pair0 / 30;
    const int p1 = pair1 % 30, a1 = pair1 / 30;
    const int p2 = pair2 % 30, a2 = pair2 / 30;

    float* acc0 = acc + pair0;
    float* acc1 = acc + pair1;
    float* acc2 = acc + pair2;

    for (int chunk = 0; chunk < 1024 / TC; ++chunk) {
        const int t0 = chunk * TC;

        // ---- stage amp transposed into [t][a] (pitch 53) ----
        for (int idx = tid; idx < 50 * (TC / 4); idx += NTHREADS) {
            const int a  = idx / (TC / 4);
            const int tq = idx % (TC / 4);
            const float4 v = *(const float4*)(amp_base + a * (20 * 1024) + t0 + tq * 4);
            const int tt = tq * 4;
            ampT[(tt + 0) * AMPT_PITCH + a] = v.x;
            ampT[(tt + 1) * AMPT_PITCH + a] = v.y;
            ampT[(tt + 2) * AMPT_PITCH + a] = v.z;
            ampT[(tt + 3) * AMPT_PITCH + a] = v.w;
        }

        // ---- stage bins (u8, pitch 132) + counts ----
        for (int idx = tid; idx < 30 * TC; idx += NTHREADS) {
            const int p  = idx / TC;
            const int tt = idx % TC;
            const float v = pha_base[p * (20 * 1024) + t0 + tt];
            int i = 0;
            #pragma unroll
            for (int j = 0; j < 19; ++j) i += (cutr[j] < v) ? 1 : 0;
            int b = i - 1;
            b = (b < 0) ? 0 : ((b > 17) ? 17 : b);
            bins[p * 132 + tt] = (unsigned char)b;
            atomicAdd(&counts[p * NB + b], 1);
        }
        __syncthreads();

        // ---- scatter-accumulate ----
        #pragma unroll 2
        for (int tq = 0; tq < TC / 4; ++tq) {
            const unsigned w0 = bins32[p0 * 33 + tq];
            const unsigned w1 = bins32[p1 * 33 + tq];
            unsigned w2 = 0;
            if (has2) w2 = bins32[p2 * 33 + tq];
            #pragma unroll
            for (int i = 0; i < 4; ++i) {
                const int tt = tq * 4 + i;
                const int k0 = (w0 >> (8 * i)) & 0xFF;
                acc0[k0 * ACC_PITCH] += ampT[tt * AMPT_PITCH + a0];
                const int k1 = (w1 >> (8 * i)) & 0xFF;
                acc1[k1 * ACC_PITCH] += ampT[tt * AMPT_PITCH + a1];
                if (has2) {
                    const int k2 = (w2 >> (8 * i)) & 0xFF;
                    acc2[k2 * ACC_PITCH] += ampT[tt * AMPT_PITCH + a2];
                }
            }
        }
        __syncthreads();
    }

    // ---- epilogue: means -> probs -> entropy -> MI, per pair ----
    const float eps = 1e-9f;
    const float LOG18 = 2.8903717578961645f;
    const float INV_LOG18 = 1.0f / 2.8903717578961645f;
    for (int pair = tid; pair < NPAIR; pair += NTHREADS) {
        const int p = pair % 30;
        float means[NB];
        float ssum = 0.0f;
        #pragma unroll
        for (int k = 0; k < NB; ++k) {
            const float cnt = (float)counts[p * NB + k];
            const float m = acc[k * ACC_PITCH + pair] / (cnt + eps);
            means[k] = m;
            ssum += m;
        }
        const float inv = 1.0f / (ssum + eps);
        float ent = 0.0f;
        #pragma unroll
        for (int k = 0; k < NB; ++k) {
            const float pr = means[k] * inv;
            ent += pr * logf(pr + eps);
        }
        g_mi[(size_t)blockIdx.x * NPAIR + pair] = (LOG18 + ent) * INV_LOG18;
    }
}

__global__ void reduce_kernel(float* __restrict__ out)
{
    const int o = blockIdx.x * 256 + threadIdx.x;
    if (o >= 48000) return;
    const int bc  = o / 1500;
    const int rem = o % 1500;
    const int p = rem / 50;
    const int a = rem % 50;
    const int pair = a * 30 + p;
    float sum = 0.0f;
    #pragma unroll
    for (int s = 0; s < 20; ++s)
        sum += g_mi[(size_t)(bc * 20 + s) * NPAIR + pair];
    out[o] = sum * 0.05f;
}

extern "C" void kernel_launch(void* const* d_in, const int* in_sizes, int n_in,
                              void* d_out, int out_size)
{
    const float* pha = (const float*)d_in[0];
    const float* amp = (const float*)d_in[1];
    const float* cut = (const float*)d_in[2];

    cudaFuncSetAttribute(mi_kernel, cudaFuncAttributeMaxDynamicSharedMemorySize, SMEM_BYTES);
    mi_kernel<<<NBLOCKS, NTHREADS, SMEM_BYTES>>>(pha, amp, cut);
    reduce_kernel<<<(48000 + 255) / 256, 256>>>((float*)d_out);
}